// round 17
// baseline (speedup 1.0000x reference)
#include <cuda_runtime.h>
#include <cuda_bf16.h>
#include <math.h>
#include <stdint.h>

// ---------------- problem constants ----------------
#define NIMG 4        // (map m, batch b) -> img = m*2+b
#define LTOK 9216     // 96*96
#define D 256
#define NH 8
#define HD 32
#define WGRID 12      // 96/8
#define NWIN 144
#define WTOK 64
#define KSEL 8
#define CN 16
#define NREPAD 640    // rep rows padded to tile multiple (576 -> 640)

// weight-plane buffer offsets (elements, per layer)
#define WOQ 0
#define WOK 65536
#define WOV 131072
#define WOM 196608
#define WO1 262144
#define WO2 524288
#define WTOT 655360

// ---------------- scratch (device globals; no allocation allowed) ----------
__device__ float g_phi_q[NIMG*LTOK*D];
__device__ float g_phi_k[NIMG*LTOK*D];
__device__ float g_v    [NIMG*LTOK*D];
__device__ float g_repn [NIMG*NWIN*D];
__device__ float g_phikr[NIMG*NWIN*D];
__device__ float g_vr   [NIMG*NWIN*D];
__device__ float g_sim  [NIMG*NWIN*NWIN];
__device__ int   g_sel  [NIMG*NWIN*KSEL];
__device__ float g_KVwin[NIMG*NWIN*NH*HD*HD];
__device__ float g_kswin[NIMG*NWIN*D];
__device__ float g_KVtot[NIMG*NH*HD*HD];
__device__ float g_kstot[NIMG*D];

// bf16 hi/lo operand planes (aligned for 16B loads). Zero-initialized,
// pad rows (rep 576..639) stay zero forever.
__device__ __align__(128) __nv_bfloat16 b_feat_hi[NIMG*LTOK*D];
__device__ __align__(128) __nv_bfloat16 b_feat_lo[NIMG*LTOK*D];
__device__ __align__(128) __nv_bfloat16 b_rep_hi [NREPAD*D];
__device__ __align__(128) __nv_bfloat16 b_rep_lo [NREPAD*D];
__device__ __align__(128) __nv_bfloat16 b_msg_hi [NIMG*LTOK*D];
__device__ __align__(128) __nv_bfloat16 b_msg_lo [NIMG*LTOK*D];
__device__ __align__(128) __nv_bfloat16 b_hcat_hi[NIMG*LTOK*2*D];
__device__ __align__(128) __nv_bfloat16 b_hcat_lo[NIMG*LTOK*2*D];
__device__ __align__(128) __nv_bfloat16 b_hid_hi [NIMG*LTOK*2*D];
__device__ __align__(128) __nv_bfloat16 b_hid_lo [NIMG*LTOK*2*D];
__device__ __align__(128) __nv_bfloat16 b_w_hi   [2*WTOT];   // both layers
__device__ __align__(128) __nv_bfloat16 b_w_lo   [2*WTOT];

// ---------------- helpers ----------------
__device__ __forceinline__ float phi(float x){ return x > 0.f ? x + 1.f : expf(x); }

__device__ __forceinline__ void split_bf16(float x, __nv_bfloat16& h, __nv_bfloat16& l){
  h = __float2bfloat16(x);
  l = __float2bfloat16(x - __bfloat162float(h));
}

__device__ __forceinline__ float blockReduceSum(float val, float* sbuf){
  __syncthreads();
  int lane = threadIdx.x & 31, wid = threadIdx.x >> 5;
  #pragma unroll
  for (int o = 16; o; o >>= 1) val += __shfl_down_sync(0xffffffffu, val, o);
  if (lane == 0) sbuf[wid] = val;
  __syncthreads();
  float r = (threadIdx.x < (blockDim.x >> 5)) ? sbuf[threadIdx.x] : 0.f;
  if (wid == 0){
    #pragma unroll
    for (int o = 16; o; o >>= 1) r += __shfl_down_sync(0xffffffffu, r, o);
    if (lane == 0) sbuf[0] = r;
  }
  __syncthreads();
  return sbuf[0];
}

__device__ __forceinline__ int spatial_l(int win, int t){
  int wy = win / WGRID, wx = win % WGRID;
  return (wy*8 + (t >> 3))*96 + wx*8 + (t & 7);
}

// ---------------- converters ----------------
// both layers at once: i in [0, 2*WTOT)
__global__ void k_convw(const float* __restrict__ q, const float* __restrict__ k,
                        const float* __restrict__ v, const float* __restrict__ m,
                        const float* __restrict__ w1, const float* __restrict__ w2){
  for (int i = blockIdx.x*blockDim.x + threadIdx.x; i < 2*WTOT;
       i += gridDim.x*blockDim.x){
    int layer = i / WTOT, j = i % WTOT;
    size_t o1 = (size_t)layer*D*D;           // 65536
    size_t o2 = (size_t)layer*2*D*2*D;       // 262144
    size_t o3 = (size_t)layer*D*2*D;         // 131072
    float x;
    if      (j < WOK) x = q[o1 + j];
    else if (j < WOV) x = k[o1 + j - WOK];
    else if (j < WOM) x = v[o1 + j - WOV];
    else if (j < WO1) x = m[o1 + j - WOM];
    else if (j < WO2) x = w1[o2 + j - WO1];
    else              x = w2[o3 + j - WO2];
    split_bf16(x, b_w_hi[i], b_w_lo[i]);
  }
}

// feat planes + hcat feat-half (cols 0..255)
__global__ void k_convfeat(const float* __restrict__ f0, const float* __restrict__ f1){
  const int half = 2*LTOK*D;
  for (int i = blockIdx.x*blockDim.x + threadIdx.x; i < NIMG*LTOK*D;
       i += gridDim.x*blockDim.x){
    float x = (i < half) ? f0[i] : f1[i - half];
    __nv_bfloat16 h, l;
    split_bf16(x, h, l);
    b_feat_hi[i] = h; b_feat_lo[i] = l;
    size_t row = (size_t)(i >> 8); int c = i & 255;
    size_t ho = (row << 9) + c;
    b_hcat_hi[ho] = h; b_hcat_lo[ho] = l;
  }
}

// ---------------- 1) per-window rep ----------------
__global__ void __launch_bounds__(256) k_rep(const float* __restrict__ f0,
                                             const float* __restrict__ f1,
                                             const float* __restrict__ conv_w){
  int img = blockIdx.x / NWIN, win = blockIdx.x % NWIN;
  int m = img >> 1, b = img & 1;
  const float* F = (m ? f1 : f0) + (size_t)b*LTOK*D;
  __shared__ float cw[CN*D];
  __shared__ float simall[WTOK*CN];
  __shared__ float avg[CN];
  __shared__ float red[32];
  int tid = threadIdx.x;
  for (int i = tid; i < CN*D; i += 256) cw[i] = conv_w[i];
  __syncthreads();
  int warp = tid >> 5, lane = tid & 31;
  for (int p = 0; p < 8; p++){
    int t = warp + p*8;
    int l = spatial_l(win, t);
    const float* fr = F + (size_t)l*D;
    float fv[8];
    #pragma unroll
    for (int i = 0; i < 8; i++) fv[i] = fr[lane + 32*i];
    for (int c = 0; c < CN; c++){
      float s = 0.f;
      #pragma unroll
      for (int i = 0; i < 8; i++) s += fv[i]*cw[c*D + lane + 32*i];
      #pragma unroll
      for (int o = 16; o; o >>= 1) s += __shfl_down_sync(0xffffffffu, s, o);
      if (lane == 0) simall[t*CN + c] = s;
    }
  }
  __syncthreads();
  if (tid < WTOK){
    float mx = -1e30f;
    for (int c = 0; c < CN; c++) mx = fmaxf(mx, simall[tid*CN + c]);
    float s = 0.f, e[CN];
    for (int c = 0; c < CN; c++){ e[c] = expf(simall[tid*CN + c] - mx); s += e[c]; }
    float inv = 1.f/s;
    for (int c = 0; c < CN; c++) simall[tid*CN + c] = e[c]*inv;
  }
  __syncthreads();
  if (tid < CN){
    float s = 0.f;
    for (int t = 0; t < WTOK; t++) s += simall[t*CN + tid];
    avg[tid] = s * (1.f/WTOK);
  }
  __syncthreads();
  float r = 0.f;
  for (int c = 0; c < CN; c++) r += avg[c]*cw[c*D + tid];
  size_t oi = (size_t)(img*NWIN + win)*D + tid;
  split_bf16(r, b_rep_hi[oi], b_rep_lo[oi]);
  float n2 = blockReduceSum(r*r, red);
  float nrm = fmaxf(sqrtf(n2), 1e-8f);
  g_repn[oi] = r / nrm;
}

// ---------------- 2) cosine sim (2x2 register blocking) ----------------
__global__ void k_cossim(int npairs, int self){
  const int H2 = NWIN/2;                 // 72
  long total = (long)npairs*H2*H2;
  for (long idx = (long)blockIdx.x*blockDim.x + threadIdx.x; idx < total;
       idx += (long)gridDim.x*blockDim.x){
    int p = (int)(idx/(H2*H2)); int rem = (int)(idx%(H2*H2));
    int q = (rem/H2)*2, s = (rem%H2)*2;
    const float* a0 = &g_repn[((size_t)p*NWIN + q)*D];
    const float* a1 = a0 + D;
    const float* b0 = self ? &g_repn[((size_t)p*NWIN + s)*D]
                           : &g_repn[(((size_t)(2+p))*NWIN + s)*D];
    const float* b1 = b0 + D;
    float c00 = 0.f, c01 = 0.f, c10 = 0.f, c11 = 0.f;
    #pragma unroll 4
    for (int k = 0; k < D; k += 4){
      float4 av0 = *(const float4*)&a0[k];
      float4 av1 = *(const float4*)&a1[k];
      float4 bv0 = *(const float4*)&b0[k];
      float4 bv1 = *(const float4*)&b1[k];
      c00 += av0.x*bv0.x + av0.y*bv0.y + av0.z*bv0.z + av0.w*bv0.w;
      c01 += av0.x*bv1.x + av0.y*bv1.y + av0.z*bv1.z + av0.w*bv1.w;
      c10 += av1.x*bv0.x + av1.y*bv0.y + av1.z*bv0.z + av1.w*bv0.w;
      c11 += av1.x*bv1.x + av1.y*bv1.y + av1.z*bv1.z + av1.w*bv1.w;
    }
    size_t ob = (size_t)p*NWIN*NWIN + (size_t)q*NWIN + s;
    g_sim[ob]            = c00;
    g_sim[ob + 1]        = c01;
    g_sim[ob + NWIN]     = c10;
    g_sim[ob + NWIN + 1] = c11;
  }
}

// ---------------- 3) top-K (warp per query; stable ties) --------------------
__global__ void k_topk(int self){
  int gw = (blockIdx.x*blockDim.x + threadIdx.x) >> 5;
  int lane = threadIdx.x & 31;
  if (gw >= NIMG*NWIN) return;
  int img = gw/NWIN, q = gw%NWIN;
  size_t base; int sq, ss;
  if (self){ base = (size_t)img*NWIN*NWIN; sq = NWIN; ss = 1; }
  else {
    int b = img & 1, m = img >> 1;
    base = (size_t)b*NWIN*NWIN;
    if (m == 0){ sq = NWIN; ss = 1; } else { sq = 1; ss = NWIN; }
  }
  const float* S = g_sim + base + (size_t)q*sq;
  float v0, v1, v2, v3, v4;
  v0 = S[(size_t)(lane      )*ss];
  v1 = S[(size_t)(lane +  32)*ss];
  v2 = S[(size_t)(lane +  64)*ss];
  v3 = S[(size_t)(lane +  96)*ss];
  v4 = (lane + 128 < NWIN) ? S[(size_t)(lane + 128)*ss] : -1e30f;
  for (int k = 0; k < KSEL; k++){
    float bv = v0; int bi = lane;
    if (v1 > bv){ bv = v1; bi = lane + 32; }
    if (v2 > bv){ bv = v2; bi = lane + 64; }
    if (v3 > bv){ bv = v3; bi = lane + 96; }
    if (v4 > bv){ bv = v4; bi = lane + 128; }
    #pragma unroll
    for (int o = 16; o; o >>= 1){
      float ov = __shfl_xor_sync(0xffffffffu, bv, o);
      int   oi = __shfl_xor_sync(0xffffffffu, bi, o);
      if (ov > bv || (ov == bv && oi < bi)){ bv = ov; bi = oi; }
    }
    if (lane == 0) g_sel[gw*KSEL + k] = bi;
    int wl = bi & 31, wj = bi >> 5;
    if (lane == wl){
      if      (wj == 0) v0 = -1e30f;
      else if (wj == 1) v1 = -1e30f;
      else if (wj == 2) v2 = -1e30f;
      else if (wj == 3) v3 = -1e30f;
      else              v4 = -1e30f;
    }
  }
}

// ---------------- 5) totals over all 144 rep rows ----------------
__global__ void __launch_bounds__(256) k_reptot(){
  int img = blockIdx.x >> 3, h = blockIdx.x & 7;
  __shared__ float pk[NWIN*HD];
  __shared__ float vv[NWIN*HD];
  int tid = threadIdx.x;
  for (int i = tid; i < NWIN*HD; i += 256){
    int r = i/HD, d = i%HD;
    size_t off = ((size_t)img*NWIN + r)*D + h*HD + d;
    pk[i] = g_phikr[off]; vv[i] = g_vr[off];
  }
  __syncthreads();
  for (int o = tid; o < HD*HD; o += 256){
    int d = o/HD, j = o%HD;
    float s = 0.f;
    for (int r = 0; r < NWIN; r++) s += pk[r*HD + d]*vv[r*HD + j];
    g_KVtot[((size_t)img*NH + h)*HD*HD + o] = s;
  }
  if (tid < HD){
    float s = 0.f;
    for (int r = 0; r < NWIN; r++) s += pk[r*HD + tid];
    g_kstot[(size_t)img*D + h*HD + tid] = s;
  }
}

// ====== 3xBF16 GEMM, ldmatrix + cp.async 4-stage: C = act(A @ B^T) ==========
template<int ACT>
__device__ __forceinline__ float actf(float x){
  if (ACT == 1) return x > 0.f ? x + 1.f : expf(x); // phi = elu + 1
  if (ACT == 2) return fmaxf(x, 0.f);               // relu
  return x;
}

__device__ __forceinline__ void mma_bf16(float* d, const uint32_t* a, const uint32_t* b){
  asm volatile(
    "mma.sync.aligned.m16n8k16.row.col.f32.bf16.bf16.f32 "
    "{%0,%1,%2,%3}, {%4,%5,%6,%7}, {%8,%9}, {%0,%1,%2,%3};"
    : "+f"(d[0]), "+f"(d[1]), "+f"(d[2]), "+f"(d[3])
    : "r"(a[0]), "r"(a[1]), "r"(a[2]), "r"(a[3]), "r"(b[0]), "r"(b[1]));
}

__device__ __forceinline__ void ldsm4(uint32_t* r, uint32_t a){
  asm volatile("ldmatrix.sync.aligned.m8n8.x4.shared.b16 {%0,%1,%2,%3}, [%4];"
    : "=r"(r[0]), "=r"(r[1]), "=r"(r[2]), "=r"(r[3]) : "r"(a));
}

__device__ __forceinline__ void cp16(uint32_t s, const void* g){
  asm volatile("cp.async.cg.shared.global [%0], [%1], 16;\n" :: "r"(s), "l"(g));
}
__device__ __forceinline__ void cp_commit(){ asm volatile("cp.async.commit_group;\n"); }
template<int NG> __device__ __forceinline__ void cp_wait(){
  asm volatile("cp.async.wait_group %0;\n" :: "n"(NG));
}

#define BM 128
#define BN 128
#define BK 16
#define SPH 24           // smem row stride in halves (48B; 3 x 16B units -> LDSM conflict-free)
#define PLANE_B 6144     // bytes per plane (128*48)
#define STAGE_B 24576    // bytes per stage (4 planes: Ah, Al, Bh, Bl)
#define NSTAGE 4
#define SMEM_DYN (NSTAGE*STAGE_B)   // 98304 bytes (dynamic, opt-in)

// one cp.async stage: 256 threads x 1 chunk per plane-operand
__device__ __forceinline__ void load_stage(uint32_t sb,
    const __nv_bfloat16* __restrict__ Ah, const __nv_bfloat16* __restrict__ Al,
    const __nv_bfloat16* __restrict__ Bh, const __nv_bfloat16* __restrict__ Bl,
    size_t abase, size_t bbase, int K, int k0, int tid)
{
  int row = tid >> 1, kw = tid & 1;
  uint32_t so = (uint32_t)(row*48 + kw*16);
  size_t go = (size_t)row*K + k0 + kw*8;
  cp16(sb + 0*PLANE_B + so, Ah + abase + go);
  cp16(sb + 1*PLANE_B + so, Al + abase + go);
  cp16(sb + 2*PLANE_B + so, Bh + bbase + go);
  cp16(sb + 3*PLANE_B + so, Bl + bbase + go);
  cp_commit();
}

// OUTMODE 1: hi/lo planes -> Ch/Cl (ACT), M multiple of 128.
// OUTMODE 3: fused qkv: N=768; region by bn: q(phi)/k(phi)/v. stride 256.
// OUTMODE 4: fused rep kv: N=512; region 0 -> C0 with phi, 1 -> C1. stride 256, M-guarded.
template<int ACT, int OUTMODE>
__global__ void __launch_bounds__(256, 2)
bgemm(const __nv_bfloat16* __restrict__ Ah, const __nv_bfloat16* __restrict__ Al,
      const __nv_bfloat16* __restrict__ Bh, const __nv_bfloat16* __restrict__ Bl,
      float* __restrict__ C0, float* __restrict__ C1, float* __restrict__ C2,
      __nv_bfloat16* __restrict__ Ch, __nv_bfloat16* __restrict__ Cl,
      int M, int N, int K)
{
  extern __shared__ __align__(16) char smraw[]; // NSTAGE * 24576 dynamic
  uint32_t sb0 = (uint32_t)__cvta_generic_to_shared(smraw);
  const int tid = threadIdx.x;
  const int bm = blockIdx.y*BM, bn = blockIdx.x*BN;
  const int warp = tid >> 5, lane = tid & 31;
  const int wm = (warp >> 1)*32, wn = (warp & 1)*64;
  const int grp = lane >> 2, tig = lane & 3;
  const size_t abase = (size_t)bm*K, bbase = (size_t)bn*K;

  float acc[16][4];
  #pragma unroll
  for (int f = 0; f < 16; f++)
    #pragma unroll
    for (int r = 0; r < 4; r++) acc[f][r] = 0.f;

  const int nk = K/BK;   // >= 16 for all our shapes
  load_stage(sb0,             Ah, Al, Bh, Bl, abase, bbase, K, 0,    tid);
  load_stage(sb0 +   STAGE_B, Ah, Al, Bh, Bl, abase, bbase, K, BK,   tid);
  load_stage(sb0 + 2*STAGE_B, Ah, Al, Bh, Bl, abase, bbase, K, 2*BK, tid);

  // ldmatrix lane addresses (bytes, relative to plane base)
  const uint32_t a_lane = (uint32_t)(((wm + (lane & 15))*SPH + (lane >> 4)*8)*2);
  const uint32_t b_lane = (uint32_t)(((wn + (lane & 7) + (lane >> 4)*8)*SPH
                                      + ((lane >> 3) & 1)*8)*2);

  int stg = 0;                 // stage index of tile kt
  for (int kt = 0; kt < nk; kt++){
    int rem = nk - 1 - kt;     // loads pending beyond tile kt (capped at 3)
    if      (rem >= 3) cp_wait<3>();
    else if (rem == 2) cp_wait<2>();
    else if (rem == 1) cp_wait<1>();
    else               cp_wait<0>();
    __syncthreads();
    uint32_t sb = sb0 + (uint32_t)(stg*STAGE_B);
    if (kt + 3 < nk){
      int ns = stg + 3; if (ns >= NSTAGE) ns -= NSTAGE;
      load_stage(sb0 + (uint32_t)(ns*STAGE_B), Ah, Al, Bh, Bl,
                 abase, bbase, K, (kt + 3)*BK, tid);
    }

    uint32_t ah[2][4], al[2][4];
    ldsm4(ah[0], sb + a_lane);
    ldsm4(ah[1], sb + a_lane + 768);           // +16 rows * 48B
    ldsm4(al[0], sb + PLANE_B + a_lane);
    ldsm4(al[1], sb + PLANE_B + a_lane + 768);
    #pragma unroll
    for (int jp = 0; jp < 4; jp++){
      uint32_t bh[4], bl[4];
      ldsm4(bh, sb + 2*PLANE_B + b_lane + jp*768);
      ldsm4(bl, sb + 3*PLANE_B + b_lane + jp*768);
      #pragma unroll
      for (int i = 0; i < 2; i++)
        #pragma unroll
        for (int jj = 0; jj < 2; jj++)
          mma_bf16(acc[i*8 + jp*2 + jj], ah[i], bl + jj*2);
      #pragma unroll
      for (int i = 0; i < 2; i++)
        #pragma unroll
        for (int jj = 0; jj < 2; jj++)
          mma_bf16(acc[i*8 + jp*2 + jj], al[i], bh + jj*2);
      #pragma unroll
      for (int i = 0; i < 2; i++)
        #pragma unroll
        for (int jj = 0; jj < 2; jj++)
          mma_bf16(acc[i*8 + jp*2 + jj], ah[i], bh + jj*2);
    }
    if (++stg == NSTAGE) stg = 0;
  }

  #pragma unroll
  for (int i = 0; i < 2; i++){
    int r0 = bm + wm + i*16 + grp;
    #pragma unroll
    for (int j = 0; j < 8; j++){
      const float* dd = acc[i*8 + j];
      int cc = wn + j*8 + tig*2;
      if (OUTMODE == 1){
        int c = bn + cc;
        #pragma unroll
        for (int rr = 0; rr < 2; rr++){
          float v0 = actf<ACT>(dd[rr*2]), v1 = actf<ACT>(dd[rr*2+1]);
          __nv_bfloat162 h, l;
          h.x = __float2bfloat16(v0); h.y = __float2bfloat16(v1);
          l.x = __float2bfloat16(v0 - __bfloat162float(h.x));
          l.y = __float2bfloat16(v1 - __bfloat162float(h.y));
          size_t o = (size_t)(r0 + rr*8)*N + c;
          *(__nv_bfloat162*)&Ch[o] = h;
          *(__nv_bfloat162*)&Cl[o] = l;
        }
      } else if (OUTMODE == 3){
        int reg = bn >> 8;                   // 0:q 1:k 2:v
        float* T = (reg == 0) ? C0 : ((reg == 1) ? C1 : C2);
        int c = (bn & 255) + cc;
        float v0 = (reg < 2) ? actf<1>(dd[0]) : dd[0];
        float v1 = (reg < 2) ? actf<1>(dd[1]) : dd[1];
        float v2 = (reg < 2) ? actf<1>(dd[2]) : dd[2];
        float v3 = (reg < 2) ? actf<1>(dd[3]) : dd[3];
        T[(size_t)r0*256 + c    ] = v0;
        T[(size_t)r0*256 + c + 1] = v1;
        T[(size_t)(r0+8)*256 + c    ] = v2;
        T[(size_t)(r0+8)*256 + c + 1] = v3;
      } else { // OUTMODE 4: rep kv
        int reg = bn >> 8;                   // 0: phi(k) -> C0, 1: v -> C1
        float* T = reg ? C1 : C0;
        int c = (bn & 255) + cc;
        float v0 = reg ? dd[0] : actf<1>(dd[0]);
        float v1 = reg ? dd[1] : actf<1>(dd[1]);
        float v2 = reg ? dd[2] : actf<1>(dd[2]);
        float v3 = reg ? dd[3] : actf<1>(dd[3]);
        if (r0 < M){
          T[(size_t)r0*256 + c    ] = v0;
          T[(size_t)r0*256 + c + 1] = v1;
        }
        if (r0 + 8 < M){
          T[(size_t)(r0+8)*256 + c    ] = v2;
          T[(size_t)(r0+8)*256 + c + 1] = v3;
        }
      }
    }
  }
}

// ====== bgemm2: 64x256 tile GEMM + fused row LayerNorm epilogue =============
// N fixed = 256 (full rows per block). LNMODE 1: Y=LN(acc)->hcat msg-half.
// LNMODE 2: r=F+LN(acc)->out + feat planes + hcat feat-half.
#define BM2 64
#define BN2 256
#define PLA2 3072u      // A plane bytes (64*48)
#define PLB2 12288u     // B plane bytes (256*48)
#define STAGE2 30720u   // 2*PLA2 + 2*PLB2
#define NST2 3
#define SMEM2 (NST2*STAGE2)   // 92160

__device__ __forceinline__ void load_stage2(uint32_t sb,
    const __nv_bfloat16* __restrict__ Ah, const __nv_bfloat16* __restrict__ Al,
    const __nv_bfloat16* __restrict__ Bh, const __nv_bfloat16* __restrict__ Bl,
    size_t abase, int K, int k0, int tid)
{
  if (tid < 128){
    int row = tid >> 1, kw = tid & 1;
    uint32_t so = (uint32_t)(row*48 + kw*16);
    size_t go = (size_t)row*K + k0 + kw*8;
    cp16(sb + so, Ah + abase + go);
    cp16(sb + PLA2 + so, Al + abase + go);
  }
  #pragma unroll
  for (int c = 0; c < 2; c++){
    int idx = tid*2 + c;
    int row = idx >> 1, kw = idx & 1;
    uint32_t so = (uint32_t)(row*48 + kw*16);
    size_t go = (size_t)row*K + k0 + kw*8;
    cp16(sb + 2*PLA2 + so, Bh + go);
    cp16(sb + 2*PLA2 + PLB2 + so, Bl + go);
  }
  cp_commit();
}

template<int LNMODE>
__global__ void __launch_bounds__(256, 2)
bgemm2(const __nv_bfloat16* __restrict__ Ah, const __nv_bfloat16* __restrict__ Al,
       const __nv_bfloat16* __restrict__ Bh, const __nv_bfloat16* __restrict__ Bl,
       const float* __restrict__ f0, const float* __restrict__ f1,
       float* __restrict__ outp,
       const float* __restrict__ G, const float* __restrict__ Bt,
       int K)
{
  extern __shared__ __align__(16) char smraw[]; // NST2*STAGE2 dynamic
  uint32_t sb0 = (uint32_t)__cvta_generic_to_shared(smraw);
  const int tid = threadIdx.x;
  const int bm = blockIdx.y*BM2;
  const int warp = tid >> 5, lane = tid & 31;
  const int wm = (warp >> 2)*32, wn = (warp & 3)*64;
  const int grp = lane >> 2, tig = lane & 3;
  const size_t abase = (size_t)bm*K;

  float acc[16][4];
  #pragma unroll
  for (int f = 0; f < 16; f++)
    #pragma unroll
    for (int r = 0; r < 4; r++) acc[f][r] = 0.f;

  const int nk = K/BK;
  load_stage2(sb0,          Ah, Al, Bh, Bl, abase, K, 0,  tid);
  load_stage2(sb0 + STAGE2, Ah, Al, Bh, Bl, abase, K, BK, tid);

  const uint32_t a_lane = (uint32_t)(((wm + (lane & 15))*SPH + (lane >> 4)*8)*2);
  const uint32_t b_lane = (uint32_t)(((wn + (lane & 7) + (lane >> 4)*8)*SPH
                                      + ((lane >> 3) & 1)*8)*2);

  int stg = 0;
  for (int kt = 0; kt < nk; kt++){
    if (kt + 1 < nk) cp_wait<1>(); else cp_wait<0>();
    __syncthreads();
    uint32_t sb = sb0 + (uint32_t)(stg*STAGE2);
    if (kt + 2 < nk){
      int ns = stg + 2; if (ns >= NST2) ns -= NST2;
      load_stage2(sb0 + (uint32_t)(ns*STAGE2), Ah, Al, Bh, Bl,
                  abase, K, (kt + 2)*BK, tid);
    }
    uint32_t ah[2][4], al[2][4];
    ldsm4(ah[0], sb + a_lane);
    ldsm4(ah[1], sb + a_lane + 768);
    ldsm4(al[0], sb + PLA2 + a_lane);
    ldsm4(al[1], sb + PLA2 + a_lane + 768);
    #pragma unroll
    for (int jp = 0; jp < 4; jp++){
      uint32_t bh[4], bl[4];
      ldsm4(bh, sb + 2*PLA2 + b_lane + jp*768);
      ldsm4(bl, sb + 2*PLA2 + PLB2 + b_lane + jp*768);
      #pragma unroll
      for (int i = 0; i < 2; i++)
        #pragma unroll
        for (int jj = 0; jj < 2; jj++){
          float* dd = acc[i*8 + jp*2 + jj];
          mma_bf16(dd, ah[i], bl + jj*2);
          mma_bf16(dd, al[i], bh + jj*2);
          mma_bf16(dd, ah[i], bh + jj*2);
        }
    }
    if (++stg == NST2) stg = 0;
  }

  // ---- fused LN epilogue ----
  __syncthreads();                     // all warps done with smem stages
  float* sf  = (float*)smraw;          // 64 x 260 fp32 tile
  float* sg  = sf + 64*260;
  float* sbv = sg + 256;
  sg[tid]  = G[tid];
  sbv[tid] = Bt[tid];
  #pragma unroll
  for (int i = 0; i < 2; i++){
    int rl = wm + i*16 + grp;
    #pragma unroll
    for (int j = 0; j < 8; j++){
      const float* dd = acc[i*8 + j];
      int c = wn + j*8 + tig*2;
      sf[rl*260 + c]       = dd[0];
      sf[rl*260 + c + 1]   = dd[1];
      sf[(rl+8)*260 + c]     = dd[2];
      sf[(rl+8)*260 + c + 1] = dd[3];
    }
  }
  __syncthreads();

  #pragma unroll
  for (int rr = 0; rr < 8; rr++){
    int r = warp*8 + rr;
    size_t grow = (size_t)(bm + r);
    float v[8];
    float s = 0.f;
    #pragma unroll
    for (int k = 0; k < 8; k++){ v[k] = sf[r*260 + lane + k*32]; s += v[k]; }
    #pragma unroll
    for (int o = 16; o; o >>= 1) s += __shfl_xor_sync(0xffffffffu, s, o);
    float mu = s * (1.f/256.f);
    float s2 = 0.f;
    #pragma unroll
    for (int k = 0; k < 8; k++){ v[k] -= mu; s2 += v[k]*v[k]; }
    #pragma unroll
    for (int o = 16; o; o >>= 1) s2 += __shfl_xor_sync(0xffffffffu, s2, o);
    float rs = rsqrtf(s2*(1.f/256.f) + 1e-5f);
    #pragma unroll
    for (int k = 0; k < 8; k++){
      int c = lane + k*32;
      float y = v[k]*rs*sg[c] + sbv[c];
      if (LNMODE == 1){
        size_t ho = (grow << 9) + 256 + c;
        split_bf16(y, b_hcat_hi[ho], b_hcat_lo[ho]);
      } else {
        float Fv = (grow < (size_t)2*LTOK)
                 ? f0[grow*256 + c]
                 : f1[(grow - (size_t)2*LTOK)*256 + c];
        float rv = Fv + y;
        size_t oi = grow*256 + c;
        outp[oi] = rv;
        __nv_bfloat16 h, lo;
        split_bf16(rv, h, lo);
        b_feat_hi[oi] = h; b_feat_lo[oi] = lo;
        size_t ho = (grow << 9) + c;
        b_hcat_hi[ho] = h; b_hcat_lo[ho] = lo;
      }
    }
  }
}

// ---------------- 6) per-window KV/ksum aggregates (vectorized) -------------
__global__ void __launch_bounds__(256) k_winagg(){
  int bid = blockIdx.x;
  int h = bid & 7; int wv = bid >> 3;
  int win = wv % NWIN, img = wv / NWIN;
  __shared__ float pk[WTOK*HD];
  __shared__ float vv[WTOK*HD];
  int tid = threadIdx.x;
  #pragma unroll
  for (int i = tid; i < WTOK*HD/4; i += 256){
    int t = i >> 3, d4 = (i & 7)*4;
    int l = spatial_l(win, t);
    size_t off = ((size_t)img*LTOK + l)*D + h*HD + d4;
    *(float4*)&pk[t*HD + d4] = *(const float4*)&g_phi_k[off];
    *(float4*)&vv[t*HD + d4] = *(const float4*)&g_v[off];
  }
  __syncthreads();
  int d = tid >> 3, j0 = (tid & 7)*4;
  float a0 = 0.f, a1 = 0.f, a2 = 0.f, a3 = 0.f;
  #pragma unroll 8
  for (int t = 0; t < WTOK; t++){
    float p = pk[t*HD + d];
    float4 v4 = *(const float4*)&vv[t*HD + j0];
    a0 += p*v4.x; a1 += p*v4.y; a2 += p*v4.z; a3 += p*v4.w;
  }
  size_t ob = (((size_t)(img*NWIN + win))*NH + h)*HD*HD + (size_t)d*HD + j0;
  *(float4*)&g_KVwin[ob] = make_float4(a0, a1, a2, a3);
  if (tid < HD){
    float s = 0.f;
    for (int t = 0; t < WTOK; t++) s += pk[t*HD + tid];
    g_kswin[((size_t)img*NWIN + win)*D + h*HD + tid] = s;
  }
}

// ---------------- 7) attention: register-resident KV build + apply ----------
__global__ void __launch_bounds__(256) k_attn(int layer){
  int img = blockIdx.x / NWIN, q = blockIdx.x % NWIN;
  int src = (layer == 0) ? img : (img ^ 2); // cross: flip map, keep batch
  __shared__ float bufpk[KSEL][D]; // 8KB
  __shared__ float bufv [KSEL][D]; // 8KB
  __shared__ int   wsel[KSEL];
  int tid = threadIdx.x;
  if (tid < KSEL) wsel[tid] = g_sel[(img*NWIN + q)*KSEL + tid];
  __syncthreads();
  #pragma unroll
  for (int k = 0; k < KSEL; k++){
    int w = wsel[k];
    bufpk[k][tid] = g_phikr[((size_t)src*NWIN + w)*D + tid];
    bufv [k][tid] = g_vr   [((size_t)src*NWIN + w)*D + tid];
  }
  __syncthreads();

  int h = tid >> 5, lane = tid & 31;
  float kvreg[32];
  const float* KVT = g_KVtot + (size_t)src*NH*HD*HD + h*HD*HD;
  #pragma unroll
  for (int d = 0; d < 32; d++) kvreg[d] = KVT[d*HD + lane];
  float ksv = g_kstot[(size_t)src*D + h*HD + lane];
  for (int k = 0; k < KSEL; k++){
    int w = wsel[k];
    const float* KVW = g_KVwin + ((size_t)(src*NWIN + w))*NH*HD*HD + h*HD*HD;
    float vj = bufv[k][h*HD + lane];
    #pragma unroll
    for (int d = 0; d < 32; d++)
      kvreg[d] += KVW[d*HD + lane] - bufpk[k][h*HD + d]*vj;
    ksv += g_kswin[((size_t)src*NWIN + w)*D + h*HD + lane] - bufpk[k][h*HD + lane];
  }

  const float* pqb = g_phi_q + (size_t)img*LTOK*D + h*HD + lane;
  for (int t = 0; t < WTOK; t++){
    int l = spatial_l(q, t);
    float pqv = __ldg(pqb + (size_t)l*D);
    float n0 = 0.f, n1 = 0.f, n2 = 0.f, n3 = 0.f;
    #pragma unroll
    for (int d = 0; d < 32; d += 4){
      float p0 = __shfl_sync(0xffffffffu, pqv, d    );
      float p1 = __shfl_sync(0xffffffffu, pqv, d + 1);
      float p2 = __shfl_sync(0xffffffffu, pqv, d + 2);
      float p3 = __shfl_sync(0xffffffffu, pqv, d + 3);
      n0 += p0*kvreg[d];   n1 += p1*kvreg[d+1];
      n2 += p2*kvreg[d+2]; n3 += p3*kvreg[d+3];
    }
    float num = (n0 + n1) + (n2 + n3);
    float dv = pqv*ksv;
    #pragma unroll
    for (int o = 16; o; o >>= 1) dv += __shfl_xor_sync(0xffffffffu, dv, o);
    float r = num / (dv + 1e-6f);
    size_t oi = ((size_t)img*LTOK + l)*D + h*HD + lane;
    split_bf16(r, b_msg_hi[oi], b_msg_lo[oi]);
  }
}

// ---------------- host ----------------
extern "C" void kernel_launch(void* const* d_in, const int* in_sizes, int n_in,
                              void* d_out, int out_size){
  (void)in_sizes; (void)n_in; (void)out_size;
  const float* feat0 = (const float*)d_in[0];
  const float* feat1 = (const float*)d_in[1];
  const float* qW    = (const float*)d_in[8];
  const float* kW    = (const float*)d_in[9];
  const float* vW    = (const float*)d_in[10];
  const float* mW    = (const float*)d_in[11];
  const float* mlpW1 = (const float*)d_in[12];
  const float* mlpW2 = (const float*)d_in[13];
  const float* n1g   = (const float*)d_in[14];
  const float* n1b   = (const float*)d_in[15];
  const float* n2g   = (const float*)d_in[16];
  const float* n2b   = (const float*)d_in[17];
  const float* conv_w= (const float*)d_in[18];
  float* out = (float*)d_out;

  cudaFuncSetAttribute((const void*)bgemm<0,3>, cudaFuncAttributeMaxDynamicSharedMemorySize, SMEM_DYN);
  cudaFuncSetAttribute((const void*)bgemm<0,4>, cudaFuncAttributeMaxDynamicSharedMemorySize, SMEM_DYN);
  cudaFuncSetAttribute((const void*)bgemm<2,1>, cudaFuncAttributeMaxDynamicSharedMemorySize, SMEM_DYN);
  cudaFuncSetAttribute((const void*)bgemm2<1>, cudaFuncAttributeMaxDynamicSharedMemorySize, SMEM2);
  cudaFuncSetAttribute((const void*)bgemm2<2>, cudaFuncAttributeMaxDynamicSharedMemorySize, SMEM2);

  float *p_phiq, *p_phik, *p_v, *p_phikr, *p_vr;
  __nv_bfloat16 *p_fh, *p_fl, *p_rh, *p_rl, *p_mh, *p_ml, *p_ch, *p_cl,
                *p_hh, *p_hl, *p_wh, *p_wl;
  cudaGetSymbolAddress((void**)&p_phiq, g_phi_q);
  cudaGetSymbolAddress((void**)&p_phik, g_phi_k);
  cudaGetSymbolAddress((void**)&p_v,    g_v);
  cudaGetSymbolAddress((void**)&p_phikr,g_phikr);
  cudaGetSymbolAddress((void**)&p_vr,   g_vr);
  cudaGetSymbolAddress((void**)&p_fh, b_feat_hi); cudaGetSymbolAddress((void**)&p_fl, b_feat_lo);
  cudaGetSymbolAddress((void**)&p_rh, b_rep_hi);  cudaGetSymbolAddress((void**)&p_rl, b_rep_lo);
  cudaGetSymbolAddress((void**)&p_mh, b_msg_hi);  cudaGetSymbolAddress((void**)&p_ml, b_msg_lo);
  cudaGetSymbolAddress((void**)&p_ch, b_hcat_hi); cudaGetSymbolAddress((void**)&p_cl, b_hcat_lo);
  cudaGetSymbolAddress((void**)&p_hh, b_hid_hi);  cudaGetSymbolAddress((void**)&p_hl, b_hid_lo);
  cudaGetSymbolAddress((void**)&p_wh, b_w_hi);    cudaGetSymbolAddress((void**)&p_wl, b_w_lo);

  const int Mall = NIMG*LTOK;   // 36864
  const int Mrep = NIMG*NWIN;   // 576 (buffers padded to 640)

  // convert BOTH layers' weights once
  k_convw<<<1280, 256>>>(qW, kW, vW, mW, mlpW1, mlpW2);

  for (int layer = 0; layer < 2; layer++){
    const float* F0 = layer ? out : feat0;
    const float* F1 = layer ? out + (size_t)2*LTOK*D : feat1;
    int self = (layer == 0);
    int npairs = self ? NIMG : 2;
    const size_t wofs = (size_t)layer*WTOT;

    if (layer == 0) k_convfeat<<<4096, 256>>>(feat0, feat1);

    k_rep<<<NIMG*NWIN, 256>>>(F0, F1, conv_w);
    {
      int total = npairs*(NWIN/2)*(NWIN/2);
      k_cossim<<<(total + 255)/256, 256>>>(npairs, self);
    }
    k_topk<<<(NIMG*NWIN*32 + 255)/256, 256>>>(self);

    // fused rep k/v projection (N=512, rows padded to 640)
    bgemm<0,4><<<dim3(4, NREPAD/BM), 256, SMEM_DYN>>>(p_rh, p_rl,
                                            p_wh + wofs + WOK, p_wl + wofs + WOK,
                                            p_phikr, p_vr, nullptr, nullptr, nullptr,
                                            Mrep, 512, D);
    k_reptot<<<NIMG*NH, 256>>>();

    // fused q/k/v projection over ALL images (M=36864, N=768)
    bgemm<0,3><<<dim3(6, Mall/BM), 256, SMEM_DYN>>>(p_fh, p_fl,
                                          p_wh + wofs + WOQ, p_wl + wofs + WOQ,
                                          p_phiq, p_phik, p_v, nullptr, nullptr,
                                          Mall, 3*D, D);

    k_winagg<<<NIMG*NWIN*NH, 256>>>();
    k_attn<<<NIMG*NWIN, 256>>>(layer);

    // mW GEMM + LN1 + hcat msg-half (fused)
    bgemm2<1><<<dim3(1, Mall/BM2), 256, SMEM2>>>(p_mh, p_ml,
                                          p_wh + wofs + WOM, p_wl + wofs + WOM,
                                          nullptr, nullptr, nullptr,
                                          n1g + layer*D, n1b + layer*D, D);

    // MLP1 (relu -> hid planes)
    bgemm<2,1><<<dim3(4, Mall/BM), 256, SMEM_DYN>>>(p_ch, p_cl,
                                          p_wh + wofs + WO1, p_wl + wofs + WO1,
                                          nullptr, nullptr, nullptr, p_hh, p_hl,
                                          Mall, 2*D, 2*D);
    // MLP2 GEMM + LN2 + residual + out/feat/hcat planes (fused)
    bgemm2<2><<<dim3(1, Mall/BM2), 256, SMEM2>>>(p_hh, p_hl,
                                          p_wh + wofs + WO2, p_wl + wofs + WO2,
                                          F0, F1, out,
                                          n2g + layer*D, n2b + layer*D, 2*D);
  }
}